// round 6
// baseline (speedup 1.0000x reference)
#include <cuda_runtime.h>
#include <math.h>

#define NLEV 3
#define NBMAX 16
#define MAXB 64
#define NCLS 80
// blocks per image-level over 3*HW cells, 128 threads:
// lev0: 3*2704=8112 -> 64 blocks (8192), lev1: 2028 -> 16 (2048), lev2: 507 -> 4 (512)
#define LB0 64
#define LB1 16
#define LB2 4
#define LBPI (LB0 + LB1 + LB2)   // 84 -> N=16 => 1344 blocks

__constant__ float c_stride[NLEV] = {8.f, 16.f, 32.f};
__constant__ float c_anchor[NLEV][3][2] = {
    {{12.f, 16.f}, {19.f, 36.f}, {40.f, 28.f}},
    {{36.f, 75.f}, {76.f, 55.f}, {72.f, 146.f}},
    {{142.f, 110.f}, {192.f, 243.f}, {459.f, 401.f}}
};
__constant__ unsigned c_grpsize[NLEV] = {LB0, LB1, LB2};

// Persistent scratch; statically zero-initialized, and the finalize branch
// resets everything it dirtied so each graph replay starts clean.
__device__ float4   g_boxes[NLEV][NBMAX][MAXB];
__device__ float    g_area [NLEV][NBMAX][MAXB];
__device__ int      g_count[NLEV][NBMAX];
__device__ unsigned g_grp  [NLEV][NBMAX];
__device__ double   g_acc[3];
__device__ unsigned g_done;

__device__ __forceinline__ float bce_logits(float x, float t) {
    return fmaxf(x, 0.f) - x * t + __logf(1.f + __expf(-fabsf(x)));
}

__global__ void __launch_bounds__(128, 12)
k_yolo(const float* __restrict__ f0, const float* __restrict__ f1,
       const float* __restrict__ f2,
       const float* __restrict__ lab0, const float* __restrict__ lab1,
       const float* __restrict__ lab2,
       int N, float* __restrict__ out) {
    // decode (image n, level, chunk)
    const int b = blockIdx.x;
    const int n = b / LBPI;
    const int r = b - n * LBPI;
    int lev, chunk, H;
    const float* feat; const float* label;
    if (r < LB0)            { lev = 0; chunk = r;             H = 52; feat = f0; label = lab0; }
    else if (r < LB0 + LB1) { lev = 1; chunk = r - LB0;       H = 26; feat = f1; label = lab1; }
    else                    { lev = 2; chunk = r - LB0 - LB1; H = 13; feat = f2; label = lab2; }
    const int W = H, HW = H * W;

    const int idx = chunk * 128 + threadIdx.x;   // a*HW + hw (feature-coalesced)
    const bool active = idx < 3 * HW;

    // ---- Phase A: issue my loads (conf first), gather positives ----
    int a = 0, hw = 0;
    size_t lb = 0;
    float lc = 0.f, rx = 0.f, ry = 0.f, rw = 0.f, rh = 0.f, rc = 0.f;
    if (active) {
        a  = idx / HW;
        hw = idx - a * HW;
        lb = ((size_t)(n * HW + hw) * 3 + a) * 85;
        lc = __ldg(label + lb + 4);              // strided: issue first

        const float* fb = feat + ((size_t)(n * 255 + a * 85)) * HW + hw;
        rx = fb[0];
        ry = fb[(size_t)HW];
        rw = fb[(size_t)2 * HW];
        rh = fb[(size_t)3 * HW];
        rc = fb[(size_t)4 * HW];

        if (lc > 0.f) {                          // rare (~0.08%)
            const float x = __ldg(label + lb + 0);
            const float y = __ldg(label + lb + 1);
            const float w = __ldg(label + lb + 2);
            const float h = __ldg(label + lb + 3);
            const int slot = atomicAdd(&g_count[lev][n], 1);
            if (slot < MAXB) {
                g_boxes[lev][n][slot] = make_float4(x - 0.5f * w, y - 0.5f * h,
                                                    x + 0.5f * w, y + 0.5f * h);
                g_area[lev][n][slot] = w * h;
            }
        }
    }

    // ---- per-(lev,image) group barrier (64/16/4 blocks) ----
    __threadfence();
    __syncthreads();
    if (threadIdx.x == 0) {
        const unsigned gs = c_grpsize[lev];
        atomicAdd(&g_grp[lev][n], 1u);
        volatile unsigned* p = &g_grp[lev][n];
        while (*p < gs) { __nanosleep(64); }
        __threadfence();
    }
    __syncthreads();

    // ---- boxes into smem ----
    __shared__ float4 s_box[MAXB];
    __shared__ float  s_area[MAXB];
    const int cnt = min(g_count[lev][n], MAXB);
    if (threadIdx.x < cnt) {
        s_box[threadIdx.x]  = g_boxes[lev][n][threadIdx.x];
        s_area[threadIdx.x] = g_area[lev][n][threadIdx.x];
    }
    __syncthreads();

    // ---- Phase B: loss ----
    float r_reg = 0.f, r_conf = 0.f, r_prob = 0.f;
    if (active) {
        const float gx = (float)(hw % W);
        const float gy = (float)(hw / W);
        const float stride = c_stride[lev];
        const float aw = c_anchor[lev][a][0];
        const float ah = c_anchor[lev][a][1];
        const bool pos = lc > 0.f;

        bool ignore = true;
        if (cnt > 0) {
            const float px = (__fdividef(1.f, 1.f + __expf(-rx)) + gx) * stride;
            const float py = (__fdividef(1.f, 1.f + __expf(-ry)) + gy) * stride;
            const float pw = __expf(rw) * aw;
            const float ph = __expf(rh) * ah;
            const float px1 = px - 0.5f * pw, py1 = py - 0.5f * ph;
            const float px2 = px + 0.5f * pw, py2 = py + 0.5f * ph;
            const float pa = pw * ph;
            // ignore = (max_iou < 0.5); iou<0.5 <=> 2*inter < max(union,1e-9)
            #pragma unroll 4
            for (int k = 0; k < cnt; k++) {
                float4 t = s_box[k];
                float iw = fmaxf(fminf(px2, t.z) - fmaxf(px1, t.x), 0.f);
                float ih = fmaxf(fminf(py2, t.w) - fmaxf(py1, t.y), 0.f);
                float inter = iw * ih;
                float uni = fmaxf(pa + s_area[k] - inter, 1e-9f);
                if (2.f * inter >= uni) ignore = false;
            }
        }

        const float bc = bce_logits(rc, pos ? 1.f : 0.f);
        r_conf = pos ? bc : (ignore ? bc : 0.f);

        if (pos) {   // rare path; label sector hot in L1/L2 from phase A
            const float lx = __ldg(label + lb + 0);
            const float ly = __ldg(label + lb + 1);
            const float lw = __ldg(label + lb + 2);
            const float lh = __ldg(label + lb + 3);
            const float scale = 2.f - lw * lh * (1.f / (416.f * 416.f));
            const float inv_s = __fdividef(1.f, stride);
            const float ox = lx * inv_s - gx;
            const float oy = ly * inv_s - gy;
            float xy = bce_logits(rx, ox) + bce_logits(ry, oy);
            const float wx = __logf(__fdividef(lw, aw) + 1e-7f);
            const float wy = __logf(__fdividef(lh, ah) + 1e-7f);
            const float dwx = rw - wx, dwy = rh - wy;
            r_reg = scale * (xy + 0.5f * (dwx * dwx + dwy * dwy));

            const float* fb = feat + ((size_t)(n * 255 + a * 85)) * HW + hw;
            float ps = 0.f;
            #pragma unroll 4
            for (int c = 0; c < NCLS; c++) {
                float rp = fb[(size_t)(5 + c) * HW];
                float lp = __ldg(label + lb + 5 + c);
                ps += bce_logits(rp, lp);
            }
            r_prob = ps;
        }
    }

    // ---- block reduction (4 warps) + last-block finalize ----
    #pragma unroll
    for (int o = 16; o; o >>= 1) {
        r_reg  += __shfl_xor_sync(0xffffffffu, r_reg,  o);
        r_conf += __shfl_xor_sync(0xffffffffu, r_conf, o);
        r_prob += __shfl_xor_sync(0xffffffffu, r_prob, o);
    }
    __shared__ float s_r[4], s_c[4], s_p[4];
    const int warp = threadIdx.x >> 5, lane = threadIdx.x & 31;
    if (lane == 0) { s_r[warp] = r_reg; s_c[warp] = r_conf; s_p[warp] = r_prob; }
    __syncthreads();

    if (threadIdx.x == 0) {
        float R = s_r[0] + s_r[1] + s_r[2] + s_r[3];
        float C = s_c[0] + s_c[1] + s_c[2] + s_c[3];
        float P = s_p[0] + s_p[1] + s_p[2] + s_p[3];
        atomicAdd(&g_acc[0], (double)R);
        atomicAdd(&g_acc[1], (double)C);
        atomicAdd(&g_acc[2], (double)P);

        __threadfence();
        unsigned t = atomicAdd(&g_done, 1u);
        if (t == (unsigned)gridDim.x - 1u) {
            double v0 = atomicAdd(&g_acc[0], 0.0);
            double v1 = atomicAdd(&g_acc[1], 0.0);
            double v2 = atomicAdd(&g_acc[2], 0.0);
            double invN = 1.0 / (double)N;
            out[0] = (float)(v0 * invN);
            out[1] = (float)(v1 * invN);
            out[2] = (float)(v2 * invN);
            g_acc[0] = 0.0; g_acc[1] = 0.0; g_acc[2] = 0.0;
            #pragma unroll
            for (int l = 0; l < NLEV; l++)
                #pragma unroll
                for (int m = 0; m < NBMAX; m++) { g_count[l][m] = 0; g_grp[l][m] = 0u; }
            g_done = 0u;
            __threadfence();
        }
    }
}

extern "C" void kernel_launch(void* const* d_in, const int* in_sizes, int n_in,
                              void* d_out, int out_size) {
    const float* f0 = (const float*)d_in[0];
    const float* f1 = (const float*)d_in[1];
    const float* f2 = (const float*)d_in[2];
    const float* l0 = (const float*)d_in[3];
    const float* l1 = (const float*)d_in[4];
    const float* l2 = (const float*)d_in[5];

    int N = in_sizes[0] / (255 * 52 * 52);
    if (N > NBMAX) N = NBMAX;

    k_yolo<<<N * LBPI, 128>>>(f0, f1, f2, l0, l1, l2, N, (float*)d_out);
}

// round 7
// speedup vs baseline: 1.3408x; 1.3408x over previous
#include <cuda_runtime.h>
#include <math.h>

#define NLEV 3
#define NBMAX 16
#define MAXB 64
#define NCLS 80
// cells per image per level (3*HW)
#define CPI0 8112
#define CPI1 2028
#define CPI2 507
#define CPI_ALL 10647
// loss blocks per image-level over 3*HW cells, 256 threads
#define LB0 32
#define LB1 8
#define LB2 2
#define LBPI (LB0 + LB1 + LB2)   // 42 -> N=16 => 672 blocks

__constant__ float c_stride[NLEV] = {8.f, 16.f, 32.f};
__constant__ float c_anchor[NLEV][3][2] = {
    {{12.f, 16.f}, {19.f, 36.f}, {40.f, 28.f}},
    {{36.f, 75.f}, {76.f, 55.f}, {72.f, 146.f}},
    {{142.f, 110.f}, {192.f, 243.f}, {459.f, 401.f}}
};

// Persistent scratch; statically zero-initialized, and the loss kernel's
// finalize branch resets everything so each graph replay starts clean.
__device__ float4 g_boxes[NLEV][NBMAX][MAXB];   // x1,y1,x2,y2 corners
__device__ float  g_area [NLEV][NBMAX][MAXB];
__device__ int    g_key  [NLEV][NBMAX][MAXB];   // cell key = a*HW + hw
__device__ int    g_count[NLEV][NBMAX];
__device__ double g_acc[3];
__device__ unsigned g_done;

__device__ __forceinline__ float bce_logits(float x, float t) {
    return fmaxf(x, 0.f) - x * t + __logf(1.f + __expf(-fabsf(x)));
}

// ---- Kernel 1: scan label conf, record positives (box corners + cell key) ----
__global__ void __launch_bounds__(256)
k_gather(const float* __restrict__ lab0, const float* __restrict__ lab1,
         const float* __restrict__ lab2, int N) {
    const int cA = N * CPI0, cB = N * CPI1;
    const int total = N * CPI_ALL;
    const int i = blockIdx.x * 256 + threadIdx.x;
    if (i >= total) return;

    int lev, j, HW;
    const float* L;
    if (i < cA)            { lev = 0; j = i;           HW = 2704; L = lab0; }
    else if (i < cA + cB)  { lev = 1; j = i - cA;      HW = 676;  L = lab1; }
    else                   { lev = 2; j = i - cA - cB; HW = 169;  L = lab2; }

    const float conf = __ldg(L + (size_t)j * 85 + 4);
    if (conf > 0.f) {                           // rare (~0.08%)
        const int n   = j / (3 * HW);
        const int rem = j - n * 3 * HW;
        const int hw  = rem / 3;
        const int a   = rem - hw * 3;
        const int slot = atomicAdd(&g_count[lev][n], 1);
        if (slot < MAXB) {
            const float* p = L + (size_t)j * 85;
            const float x = p[0], y = p[1], w = p[2], h = p[3];
            g_boxes[lev][n][slot] = make_float4(x - 0.5f * w, y - 0.5f * h,
                                                x + 0.5f * w, y + 0.5f * h);
            g_area[lev][n][slot] = w * h;
            g_key [lev][n][slot] = a * HW + hw;
        }
    }
}

// ---- Kernel 2: loss. Negatives read ONLY 5 coalesced feature floats. ----
__global__ void __launch_bounds__(256, 6)
k_loss(const float* __restrict__ f0, const float* __restrict__ f1,
       const float* __restrict__ f2,
       const float* __restrict__ lab0, const float* __restrict__ lab1,
       const float* __restrict__ lab2,
       int N, float* __restrict__ out) {
    const int b = blockIdx.x;
    const int n = b / LBPI;
    const int r = b - n * LBPI;
    int lev, chunk, H;
    const float* feat; const float* label;
    if (r < LB0)            { lev = 0; chunk = r;             H = 52; feat = f0; label = lab0; }
    else if (r < LB0 + LB1) { lev = 1; chunk = r - LB0;       H = 26; feat = f1; label = lab1; }
    else                    { lev = 2; chunk = r - LB0 - LB1; H = 13; feat = f2; label = lab2; }
    const int W = H, HW = H * W;

    const int idx = chunk * 256 + threadIdx.x;   // a*HW + hw (feature-coalesced)
    const bool active = idx < 3 * HW;

    // issue feature loads immediately (overlap with smem staging)
    int a = 0, hw = 0;
    float rx = 0.f, ry = 0.f, rw = 0.f, rh = 0.f, rc = 0.f;
    if (active) {
        a  = idx / HW;
        hw = idx - a * HW;
        const float* fb = feat + ((size_t)(n * 255 + a * 85)) * HW + hw;
        rx = fb[0];
        ry = fb[(size_t)HW];
        rw = fb[(size_t)2 * HW];
        rh = fb[(size_t)3 * HW];
        rc = fb[(size_t)4 * HW];
    }

    __shared__ float4 s_box[MAXB];
    __shared__ float  s_area[MAXB];
    __shared__ int    s_key[MAXB];
    const int cnt = min(g_count[lev][n], MAXB);
    if (threadIdx.x < cnt) {
        s_box[threadIdx.x]  = g_boxes[lev][n][threadIdx.x];
        s_area[threadIdx.x] = g_area[lev][n][threadIdx.x];
        s_key[threadIdx.x]  = g_key[lev][n][threadIdx.x];
    }
    __syncthreads();

    float r_reg = 0.f, r_conf = 0.f, r_prob = 0.f;
    if (active) {
        const float gx = (float)(hw % W);
        const float gy = (float)(hw / W);
        const float stride = c_stride[lev];
        const float aw = c_anchor[lev][a][0];
        const float ah = c_anchor[lev][a][1];

        bool pos = false, ignore = true;
        if (cnt > 0) {
            const float px = (__fdividef(1.f, 1.f + __expf(-rx)) + gx) * stride;
            const float py = (__fdividef(1.f, 1.f + __expf(-ry)) + gy) * stride;
            const float pw = __expf(rw) * aw;
            const float ph = __expf(rh) * ah;
            const float px1 = px - 0.5f * pw, py1 = py - 0.5f * ph;
            const float px2 = px + 0.5f * pw, py2 = py + 0.5f * ph;
            const float pa = pw * ph;
            // ignore = (max_iou < 0.5); iou<0.5 <=> 2*inter < max(union,1e-9)
            #pragma unroll 4
            for (int k = 0; k < cnt; k++) {
                const float4 t = s_box[k];
                float iw = fmaxf(fminf(px2, t.z) - fmaxf(px1, t.x), 0.f);
                float ih = fmaxf(fminf(py2, t.w) - fmaxf(py1, t.y), 0.f);
                const float inter = iw * ih;
                const float uni = fmaxf(pa + s_area[k] - inter, 1e-9f);
                if (2.f * inter >= uni) ignore = false;
                if (s_key[k] == idx) pos = true;
            }
        }

        const float bc = bce_logits(rc, pos ? 1.f : 0.f);
        r_conf = pos ? bc : (ignore ? bc : 0.f);

        if (pos) {   // rare path; label sector hot in L2 from k_gather
            const size_t lb = ((size_t)(n * HW + hw) * 3 + a) * 85;
            const float lx = __ldg(label + lb + 0);
            const float ly = __ldg(label + lb + 1);
            const float lw = __ldg(label + lb + 2);
            const float lh = __ldg(label + lb + 3);
            const float scale = 2.f - lw * lh * (1.f / (416.f * 416.f));
            const float inv_s = __fdividef(1.f, stride);
            const float ox = lx * inv_s - gx;
            const float oy = ly * inv_s - gy;
            float xy = bce_logits(rx, ox) + bce_logits(ry, oy);
            const float wx = __logf(__fdividef(lw, aw) + 1e-7f);
            const float wy = __logf(__fdividef(lh, ah) + 1e-7f);
            const float dwx = rw - wx, dwy = rh - wy;
            r_reg = scale * (xy + 0.5f * (dwx * dwx + dwy * dwy));

            const float* fb = feat + ((size_t)(n * 255 + a * 85)) * HW + hw;
            float ps = 0.f;
            #pragma unroll 4
            for (int c = 0; c < NCLS; c++) {
                const float rp = fb[(size_t)(5 + c) * HW];
                const float lp = __ldg(label + lb + 5 + c);
                ps += bce_logits(rp, lp);
            }
            r_prob = ps;
        }
    }

    // ---- block reduction + last-block finalize ----
    #pragma unroll
    for (int o = 16; o; o >>= 1) {
        r_reg  += __shfl_xor_sync(0xffffffffu, r_reg,  o);
        r_conf += __shfl_xor_sync(0xffffffffu, r_conf, o);
        r_prob += __shfl_xor_sync(0xffffffffu, r_prob, o);
    }
    __shared__ float s_r[8], s_c[8], s_p[8];
    const int warp = threadIdx.x >> 5, lane = threadIdx.x & 31;
    if (lane == 0) { s_r[warp] = r_reg; s_c[warp] = r_conf; s_p[warp] = r_prob; }
    __syncthreads();

    if (threadIdx.x == 0) {
        float R = 0.f, C = 0.f, P = 0.f;
        #pragma unroll
        for (int w = 0; w < 8; w++) { R += s_r[w]; C += s_c[w]; P += s_p[w]; }
        atomicAdd(&g_acc[0], (double)R);
        atomicAdd(&g_acc[1], (double)C);
        atomicAdd(&g_acc[2], (double)P);

        __threadfence();
        const unsigned t = atomicAdd(&g_done, 1u);
        if (t == (unsigned)gridDim.x - 1u) {
            const double v0 = atomicAdd(&g_acc[0], 0.0);
            const double v1 = atomicAdd(&g_acc[1], 0.0);
            const double v2 = atomicAdd(&g_acc[2], 0.0);
            const double invN = 1.0 / (double)N;
            out[0] = (float)(v0 * invN);
            out[1] = (float)(v1 * invN);
            out[2] = (float)(v2 * invN);
            g_acc[0] = 0.0; g_acc[1] = 0.0; g_acc[2] = 0.0;
            #pragma unroll
            for (int l = 0; l < NLEV; l++)
                #pragma unroll
                for (int m = 0; m < NBMAX; m++) g_count[l][m] = 0;
            g_done = 0u;
            __threadfence();
        }
    }
}

extern "C" void kernel_launch(void* const* d_in, const int* in_sizes, int n_in,
                              void* d_out, int out_size) {
    const float* f0 = (const float*)d_in[0];
    const float* f1 = (const float*)d_in[1];
    const float* f2 = (const float*)d_in[2];
    const float* l0 = (const float*)d_in[3];
    const float* l1 = (const float*)d_in[4];
    const float* l2 = (const float*)d_in[5];

    int N = in_sizes[0] / (255 * 52 * 52);
    if (N > NBMAX) N = NBMAX;

    const int gtotal = N * CPI_ALL;
    k_gather<<<(gtotal + 255) / 256, 256>>>(l0, l1, l2, N);
    k_loss<<<N * LBPI, 256>>>(f0, f1, f2, l0, l1, l2, N, (float*)d_out);
}

// round 8
// speedup vs baseline: 1.5254x; 1.1377x over previous
#include <cuda_runtime.h>
#include <math.h>

#define NLEV 3
#define NBMAX 16
#define MAXB 64
#define NCLS 80
#define PMAX 1024
// cells per image per level (3*HW)
#define CPI0 8112
#define CPI1 2028
#define CPI2 507
#define CPI_ALL 10647
// main loss blocks per image-level over 3*HW cells, 256 threads
#define LB0 32
#define LB1 8
#define LB2 2
#define LBPI (LB0 + LB1 + LB2)   // 42 -> N=16 => 672 main blocks
#define PBLK 18                  // positive-path blocks (18*8=144 warps)

__constant__ float c_stride[NLEV] = {8.f, 16.f, 32.f};
__constant__ float c_anchor[NLEV][3][2] = {
    {{12.f, 16.f}, {19.f, 36.f}, {40.f, 28.f}},
    {{36.f, 75.f}, {76.f, 55.f}, {72.f, 146.f}},
    {{142.f, 110.f}, {192.f, 243.f}, {459.f, 401.f}}
};

// Persistent scratch; statically zero-initialized; loss finalize resets all.
__device__ float4   g_boxes[NLEV][NBMAX][MAXB];   // corners x1,y1,x2,y2
__device__ float    g_area [NLEV][NBMAX][MAXB];
__device__ int      g_key  [NLEV][NBMAX][MAXB];   // cell key = a*HW + hw
__device__ int      g_count[NLEV][NBMAX];
__device__ unsigned g_plist[PMAX];                // packed (lev<<17 | n<<13 | key)
__device__ int      g_pcount;
__device__ double   g_acc[3];
__device__ unsigned g_done;

__device__ __forceinline__ float bce_logits(float x, float t) {
    return fmaxf(x, 0.f) - x * t + __logf(1.f + __expf(-fabsf(x)));
}

// ---- Kernel 1: scan label conf, record positives ----
__global__ void __launch_bounds__(256)
k_gather(const float* __restrict__ lab0, const float* __restrict__ lab1,
         const float* __restrict__ lab2, int N) {
    const int cA = N * CPI0, cB = N * CPI1;
    const int total = N * CPI_ALL;
    const int i = blockIdx.x * 256 + threadIdx.x;
    if (i >= total) return;

    int lev, j, HW;
    const float* L;
    if (i < cA)            { lev = 0; j = i;           HW = 2704; L = lab0; }
    else if (i < cA + cB)  { lev = 1; j = i - cA;      HW = 676;  L = lab1; }
    else                   { lev = 2; j = i - cA - cB; HW = 169;  L = lab2; }

    const float conf = __ldg(L + (size_t)j * 85 + 4);
    if (conf > 0.f) {                           // rare (~0.08%)
        const int n   = j / (3 * HW);
        const int rem = j - n * 3 * HW;
        const int hw  = rem / 3;
        const int a   = rem - hw * 3;
        const int key = a * HW + hw;
        const int slot = atomicAdd(&g_count[lev][n], 1);
        if (slot < MAXB) {
            const float* p = L + (size_t)j * 85;
            const float x = p[0], y = p[1], w = p[2], h = p[3];
            g_boxes[lev][n][slot] = make_float4(x - 0.5f * w, y - 0.5f * h,
                                                x + 0.5f * w, y + 0.5f * h);
            g_area[lev][n][slot] = w * h;
            g_key [lev][n][slot] = key;
        }
        const int ps = atomicAdd(&g_pcount, 1);
        if (ps < PMAX)
            g_plist[ps] = ((unsigned)lev << 17) | ((unsigned)n << 13) | (unsigned)key;
    }
}

// ---- Kernel 2: main loss (uniform path, no label reads) + positive blocks ----
__global__ void __launch_bounds__(256, 6)
k_loss(const float* __restrict__ f0, const float* __restrict__ f1,
       const float* __restrict__ f2,
       const float* __restrict__ lab0, const float* __restrict__ lab1,
       const float* __restrict__ lab2,
       int N, float* __restrict__ out) {
    const int b = blockIdx.x;
    const int nMain = N * LBPI;
    const int warp = threadIdx.x >> 5, lane = threadIdx.x & 31;

    float r_reg = 0.f, r_conf = 0.f, r_prob = 0.f;

    if (b < nMain) {
        // ================= main path: conf loss for every cell =================
        const int n = b / LBPI;
        const int r = b - n * LBPI;
        int lev, chunk, H;
        const float* feat;
        if (r < LB0)            { lev = 0; chunk = r;             H = 52; feat = f0; }
        else if (r < LB0 + LB1) { lev = 1; chunk = r - LB0;       H = 26; feat = f1; }
        else                    { lev = 2; chunk = r - LB0 - LB1; H = 13; feat = f2; }
        const int W = H, HW = H * W;

        const int idx = chunk * 256 + threadIdx.x;   // a*HW + hw
        const bool active = idx < 3 * HW;

        int a = 0, hw = 0;
        float rx = 0.f, ry = 0.f, rw = 0.f, rh = 0.f, rc = 0.f;
        if (active) {
            a  = idx / HW;
            hw = idx - a * HW;
            const float* fb = feat + ((size_t)(n * 255 + a * 85)) * HW + hw;
            rx = fb[0];
            ry = fb[(size_t)HW];
            rw = fb[(size_t)2 * HW];
            rh = fb[(size_t)3 * HW];
            rc = fb[(size_t)4 * HW];
        }

        __shared__ float4 s_box[MAXB];
        __shared__ float  s_area[MAXB];
        __shared__ int    s_key[MAXB];
        const int cnt = min(g_count[lev][n], MAXB);
        if (threadIdx.x < cnt) {
            s_box[threadIdx.x]  = g_boxes[lev][n][threadIdx.x];
            s_area[threadIdx.x] = g_area[lev][n][threadIdx.x];
            s_key[threadIdx.x]  = g_key[lev][n][threadIdx.x];
        }
        __syncthreads();

        if (active) {
            bool pos = false, ignore = true;
            if (cnt > 0) {
                const float gx = (float)(hw % W);
                const float gy = (float)(hw / W);
                const float stride = c_stride[lev];
                const float px = (__fdividef(1.f, 1.f + __expf(-rx)) + gx) * stride;
                const float py = (__fdividef(1.f, 1.f + __expf(-ry)) + gy) * stride;
                const float pw = __expf(rw) * c_anchor[lev][a][0];
                const float ph = __expf(rh) * c_anchor[lev][a][1];
                const float px1 = px - 0.5f * pw, py1 = py - 0.5f * ph;
                const float px2 = px + 0.5f * pw, py2 = py + 0.5f * ph;
                const float pa = pw * ph;
                // ignore = (max_iou < 0.5); iou<0.5 <=> 2*inter < max(union,1e-9)
                #pragma unroll 4
                for (int k = 0; k < cnt; k++) {
                    const float4 t = s_box[k];
                    const float iw = fmaxf(fminf(px2, t.z) - fmaxf(px1, t.x), 0.f);
                    const float ih = fmaxf(fminf(py2, t.w) - fmaxf(py1, t.y), 0.f);
                    const float inter = iw * ih;
                    const float uni = fmaxf(pa + s_area[k] - inter, 1e-9f);
                    if (2.f * inter >= uni) ignore = false;
                    if (s_key[k] == idx) pos = true;
                }
            }
            const float bc = bce_logits(rc, pos ? 1.f : 0.f);
            r_conf = pos ? bc : (ignore ? bc : 0.f);
        }
    } else {
        // ============ positive path: warp-per-positive, lane-per-channel ============
        const int pcount = min(g_pcount, PMAX);
        const int gw = (b - nMain) * 8 + warp;            // global warp id
        for (int p = gw; p < pcount; p += PBLK * 8) {
            const unsigned pk = g_plist[p];
            const int lev = (int)(pk >> 17);
            const int n   = (int)((pk >> 13) & 15u);
            const int key = (int)(pk & 0x1FFFu);
            int H; const float* feat; const float* label;
            if (lev == 0)      { H = 52; feat = f0; label = lab0; }
            else if (lev == 1) { H = 26; feat = f1; label = lab1; }
            else               { H = 13; feat = f2; label = lab2; }
            const int W = H, HW = H * W;
            const int a  = key / HW;
            const int hw = key - a * HW;

            const float* fb = feat + ((size_t)(n * 255 + a * 85)) * HW + hw;
            const float* Lb = label + ((size_t)(n * HW + hw) * 3 + a) * 85;

            // lanes 0-3 fetch raw xy/wh feature + label xywh; broadcast
            float fv = 0.f, lv = 0.f;
            if (lane < 4) {
                fv = fb[(size_t)lane * HW];
                lv = __ldg(Lb + lane);
            }
            const float rx = __shfl_sync(0xffffffffu, fv, 0);
            const float ry = __shfl_sync(0xffffffffu, fv, 1);
            const float rw = __shfl_sync(0xffffffffu, fv, 2);
            const float rh = __shfl_sync(0xffffffffu, fv, 3);
            const float lx = __shfl_sync(0xffffffffu, lv, 0);
            const float ly = __shfl_sync(0xffffffffu, lv, 1);
            const float lw = __shfl_sync(0xffffffffu, lv, 2);
            const float lh = __shfl_sync(0xffffffffu, lv, 3);

            // prob loss: lane handles channels lane, lane+32, lane+64
            float ps = 0.f;
            #pragma unroll
            for (int c0 = 0; c0 < NCLS; c0 += 32) {
                const int c = c0 + lane;
                if (c < NCLS) {
                    const float rp = fb[(size_t)(5 + c) * HW];
                    const float lp = __ldg(Lb + 5 + c);
                    ps += bce_logits(rp, lp);
                }
            }
            r_prob += ps;

            if (lane == 0) {
                const float gx = (float)(hw % W);
                const float gy = (float)(hw / W);
                const float stride = c_stride[lev];
                const float aw = c_anchor[lev][a][0];
                const float ah = c_anchor[lev][a][1];
                const float scale = 2.f - lw * lh * (1.f / (416.f * 416.f));
                const float inv_s = __fdividef(1.f, stride);
                const float ox = lx * inv_s - gx;
                const float oy = ly * inv_s - gy;
                const float xy = bce_logits(rx, ox) + bce_logits(ry, oy);
                const float wx = __logf(__fdividef(lw, aw) + 1e-7f);
                const float wy = __logf(__fdividef(lh, ah) + 1e-7f);
                const float dwx = rw - wx, dwy = rh - wy;
                r_reg += scale * (xy + 0.5f * (dwx * dwx + dwy * dwy));
            }
        }
        __syncthreads();   // match main-path barrier count (2 per block)
        __syncthreads();
    }

    // ---- block reduction + last-block finalize ----
    #pragma unroll
    for (int o = 16; o; o >>= 1) {
        r_reg  += __shfl_xor_sync(0xffffffffu, r_reg,  o);
        r_conf += __shfl_xor_sync(0xffffffffu, r_conf, o);
        r_prob += __shfl_xor_sync(0xffffffffu, r_prob, o);
    }
    __shared__ float s_r[8], s_c[8], s_p[8];
    if (lane == 0) { s_r[warp] = r_reg; s_c[warp] = r_conf; s_p[warp] = r_prob; }
    __syncthreads();

    if (threadIdx.x == 0) {
        float R = 0.f, C = 0.f, P = 0.f;
        #pragma unroll
        for (int w = 0; w < 8; w++) { R += s_r[w]; C += s_c[w]; P += s_p[w]; }
        atomicAdd(&g_acc[0], (double)R);
        atomicAdd(&g_acc[1], (double)C);
        atomicAdd(&g_acc[2], (double)P);

        __threadfence();
        const unsigned t = atomicAdd(&g_done, 1u);
        if (t == (unsigned)gridDim.x - 1u) {
            const double v0 = atomicAdd(&g_acc[0], 0.0);
            const double v1 = atomicAdd(&g_acc[1], 0.0);
            const double v2 = atomicAdd(&g_acc[2], 0.0);
            const double invN = 1.0 / (double)N;
            out[0] = (float)(v0 * invN);
            out[1] = (float)(v1 * invN);
            out[2] = (float)(v2 * invN);
            g_acc[0] = 0.0; g_acc[1] = 0.0; g_acc[2] = 0.0;
            #pragma unroll
            for (int l = 0; l < NLEV; l++)
                #pragma unroll
                for (int m = 0; m < NBMAX; m++) g_count[l][m] = 0;
            g_pcount = 0;
            g_done = 0u;
            __threadfence();
        }
    }
}

extern "C" void kernel_launch(void* const* d_in, const int* in_sizes, int n_in,
                              void* d_out, int out_size) {
    const float* f0 = (const float*)d_in[0];
    const float* f1 = (const float*)d_in[1];
    const float* f2 = (const float*)d_in[2];
    const float* l0 = (const float*)d_in[3];
    const float* l1 = (const float*)d_in[4];
    const float* l2 = (const float*)d_in[5];

    int N = in_sizes[0] / (255 * 52 * 52);
    if (N > NBMAX) N = NBMAX;

    const int gtotal = N * CPI_ALL;
    k_gather<<<(gtotal + 255) / 256, 256>>>(l0, l1, l2, N);
    k_loss<<<N * LBPI + PBLK, 256>>>(f0, f1, f2, l0, l1, l2, N, (float*)d_out);
}

// round 9
// speedup vs baseline: 1.5287x; 1.0021x over previous
#include <cuda_runtime.h>
#include <math.h>

#define NLEV 3
#define NBMAX 16
#define MAXB 64
#define NCLS 80
#define PMAX 1024
// cells per image per level (3*HW)
#define CPI0 8112
#define CPI1 2028
#define CPI2 507
#define CPI_ALL 10647
// main loss blocks per image: lev0 pairs 4056 -> 16, lev1 pairs 1014 -> 4, lev2 scalar 507 -> 2
#define VB0 16
#define VB1 4
#define SB2 2
#define LBPI (VB0 + VB1 + SB2)   // 22 -> N=16 => 352 main blocks
#define PBLK 18                  // positive-path blocks (144 warps)

__constant__ float c_stride[NLEV] = {8.f, 16.f, 32.f};
__constant__ float c_anchor[NLEV][3][2] = {
    {{12.f, 16.f}, {19.f, 36.f}, {40.f, 28.f}},
    {{36.f, 75.f}, {76.f, 55.f}, {72.f, 146.f}},
    {{142.f, 110.f}, {192.f, 243.f}, {459.f, 401.f}}
};

// Persistent scratch; statically zero-initialized; loss finalize resets all.
__device__ float4   g_boxes[NLEV][NBMAX][MAXB];   // corners x1,y1,x2,y2
__device__ float    g_area [NLEV][NBMAX][MAXB];   // ta/3
__device__ int      g_key  [NLEV][NBMAX][MAXB];   // cell key = a*HW + hw
__device__ int      g_count[NLEV][NBMAX];
__device__ unsigned g_plist[PMAX];                // packed (lev<<17 | n<<13 | key)
__device__ int      g_pcount;
__device__ double   g_acc[3];
__device__ unsigned g_done;

__device__ __forceinline__ float bce_logits(float x, float t) {
    return fmaxf(x, 0.f) - x * t + __logf(1.f + __expf(-fabsf(x)));
}

// ---- Kernel 1: scan label conf with MLP=4 per thread ----
__global__ void __launch_bounds__(256)
k_gather(const float* __restrict__ lab0, const float* __restrict__ lab1,
         const float* __restrict__ lab2, int N, int total) {
    const int base = blockIdx.x * 256 + threadIdx.x;
    const int step = gridDim.x * 256;
    const int cA = N * CPI0, cB = N * CPI1;

    int  ii[4]; bool ok[4];
    int  lv[4], jj[4], hh[4];
    const float* P[4];
    #pragma unroll
    for (int r = 0; r < 4; r++) {
        const int i = base + r * step;
        ii[r] = i;
        ok[r] = i < total;
        int lev, j, HW; const float* L;
        if (i < cA)            { lev = 0; j = i;           HW = 2704; L = lab0; }
        else if (i < cA + cB)  { lev = 1; j = i - cA;      HW = 676;  L = lab1; }
        else                   { lev = 2; j = i - cA - cB; HW = 169;  L = lab2; }
        lv[r] = lev; jj[r] = ok[r] ? j : 0; hh[r] = HW;
        P[r]  = (ok[r] ? L : lab0) + (size_t)jj[r] * 85;
    }
    float conf[4];
    #pragma unroll
    for (int r = 0; r < 4; r++) conf[r] = __ldg(P[r] + 4);   // 4 loads in flight

    #pragma unroll
    for (int r = 0; r < 4; r++) {
        if (ok[r] && conf[r] > 0.f) {                         // rare (~0.08%)
            const int HW = hh[r], lev = lv[r], j = jj[r];
            const int n   = j / (3 * HW);
            const int rem = j - n * 3 * HW;
            const int hw  = rem / 3;
            const int a   = rem - hw * 3;
            const int key = a * HW + hw;
            const int slot = atomicAdd(&g_count[lev][n], 1);
            if (slot < MAXB) {
                const float x = __ldg(P[r] + 0), y = __ldg(P[r] + 1);
                const float w = __ldg(P[r] + 2), h = __ldg(P[r] + 3);
                g_boxes[lev][n][slot] = make_float4(x - 0.5f * w, y - 0.5f * h,
                                                    x + 0.5f * w, y + 0.5f * h);
                g_area[lev][n][slot] = w * h * (1.f / 3.f);
                g_key [lev][n][slot] = key;
            }
            const int ps = atomicAdd(&g_pcount, 1);
            if (ps < PMAX)
                g_plist[ps] = ((unsigned)lev << 17) | ((unsigned)n << 13) | (unsigned)key;
        }
    }
}

// ---- Kernel 2: main loss (vectorized) + positive blocks ----
__global__ void __launch_bounds__(256, 4)
k_loss(const float* __restrict__ f0, const float* __restrict__ f1,
       const float* __restrict__ f2,
       const float* __restrict__ lab0, const float* __restrict__ lab1,
       const float* __restrict__ lab2,
       int N, float* __restrict__ out) {
    const int b = blockIdx.x;
    const int nMain = N * LBPI;
    const int warp = threadIdx.x >> 5, lane = threadIdx.x & 31;

    float r_reg = 0.f, r_conf = 0.f, r_prob = 0.f;

    if (b < nMain) {
        const int n = b / LBPI;
        const int r = b - n * LBPI;
        int lev, chunk, H;
        const float* feat;
        bool vec;
        if (r < VB0)            { lev = 0; chunk = r;             H = 52; feat = f0; vec = true; }
        else if (r < VB0 + VB1) { lev = 1; chunk = r - VB0;       H = 26; feat = f1; vec = true; }
        else                    { lev = 2; chunk = r - VB0 - VB1; H = 13; feat = f2; vec = false; }
        const int W = H, HW = H * W;

        // ------- issue loads first -------
        int idx0 = 0, a = 0, hw0 = 0;
        float2 rx2 = {0.f,0.f}, ry2 = {0.f,0.f}, rw2 = {0.f,0.f},
               rh2 = {0.f,0.f}, rc2 = {0.f,0.f};
        bool act;
        if (vec) {
            const int pair = chunk * 256 + threadIdx.x;
            act = pair < (3 * HW >> 1);
            if (act) {
                idx0 = pair * 2;
                a = idx0 / HW; hw0 = idx0 - a * HW;   // hw0 even, hw0+1 same row/plane
                const float* fb = feat + ((size_t)(n * 255 + a * 85)) * HW + hw0;
                rx2 = *reinterpret_cast<const float2*>(fb);
                ry2 = *reinterpret_cast<const float2*>(fb + (size_t)HW);
                rw2 = *reinterpret_cast<const float2*>(fb + (size_t)2 * HW);
                rh2 = *reinterpret_cast<const float2*>(fb + (size_t)3 * HW);
                rc2 = *reinterpret_cast<const float2*>(fb + (size_t)4 * HW);
            }
        } else {
            const int idx = chunk * 256 + threadIdx.x;
            act = idx < 3 * HW;
            if (act) {
                idx0 = idx;
                a = idx / HW; hw0 = idx - a * HW;
                const float* fb = feat + ((size_t)(n * 255 + a * 85)) * HW + hw0;
                rx2.x = fb[0];
                ry2.x = fb[(size_t)HW];
                rw2.x = fb[(size_t)2 * HW];
                rh2.x = fb[(size_t)3 * HW];
                rc2.x = fb[(size_t)4 * HW];
            }
        }

        // ------- stage boxes -------
        __shared__ float4 s_box[MAXB];
        __shared__ float  s_ta3[MAXB];
        __shared__ int    s_key[MAXB];
        const int cnt = min(g_count[lev][n], MAXB);
        if (threadIdx.x < cnt) {
            s_box[threadIdx.x] = g_boxes[lev][n][threadIdx.x];
            s_ta3[threadIdx.x] = g_area[lev][n][threadIdx.x];
            s_key[threadIdx.x] = g_key[lev][n][threadIdx.x];
        }
        __syncthreads();

        if (act) {
            const float gy  = (float)(hw0 / W);
            const float gx0 = (float)(hw0 - (hw0 / W) * W);
            const float stride = c_stride[lev];
            const float aw = c_anchor[lev][a][0];
            const float ah = c_anchor[lev][a][1];

            bool pos0 = false, pos1 = false, ign0 = true, ign1 = true;
            const int nCell = vec ? 2 : 1;
            if (cnt > 0) {
                // cell 0 box
                const float ex0 = __expf(-rx2.x), ey0 = __expf(-ry2.x);
                const float d0  = __fdividef(1.f, (1.f + ex0) * (1.f + ey0));
                const float px0 = ((1.f + ey0) * d0 + gx0) * stride;
                const float py0 = ((1.f + ex0) * d0 + gy)  * stride;
                const float pw0 = __expf(rw2.x) * aw, ph0 = __expf(rh2.x) * ah;
                const float ax1 = px0 - 0.5f * pw0, ay1 = py0 - 0.5f * ph0;
                const float ax2 = px0 + 0.5f * pw0, ay2 = py0 + 0.5f * ph0;
                const float pa3a = pw0 * ph0 * (1.f / 3.f);
                // cell 1 box
                float bx1 = 0.f, by1 = 0.f, bx2 = 0.f, by2 = 0.f, pa3b = 0.f;
                if (nCell == 2) {
                    const float ex1 = __expf(-rx2.y), ey1 = __expf(-ry2.y);
                    const float d1  = __fdividef(1.f, (1.f + ex1) * (1.f + ey1));
                    const float px1c = ((1.f + ey1) * d1 + gx0 + 1.f) * stride;
                    const float py1c = ((1.f + ex1) * d1 + gy) * stride;
                    const float pw1 = __expf(rw2.y) * aw, ph1 = __expf(rh2.y) * ah;
                    bx1 = px1c - 0.5f * pw1; by1 = py1c - 0.5f * ph1;
                    bx2 = px1c + 0.5f * pw1; by2 = py1c + 0.5f * ph1;
                    pa3b = pw1 * ph1 * (1.f / 3.f);
                }
                // iou >= 0.5  <=>  inter >= pa/3 + ta/3   (pa,ta > 0)
                #pragma unroll 2
                for (int k = 0; k < cnt; k++) {
                    const float4 t = s_box[k];
                    const float ta3 = s_ta3[k];
                    const int   key = s_key[k];
                    {
                        const float iw = fmaxf(fminf(ax2, t.z) - fmaxf(ax1, t.x), 0.f);
                        const float ih = fmaxf(fminf(ay2, t.w) - fmaxf(ay1, t.y), 0.f);
                        if (iw * ih >= pa3a + ta3) ign0 = false;
                        if (key == idx0) pos0 = true;
                    }
                    if (nCell == 2) {
                        const float iw = fmaxf(fminf(bx2, t.z) - fmaxf(bx1, t.x), 0.f);
                        const float ih = fmaxf(fminf(by2, t.w) - fmaxf(by1, t.y), 0.f);
                        if (iw * ih >= pa3b + ta3) ign1 = false;
                        if (key == idx0 + 1) pos1 = true;
                    }
                }
            }
            {
                const float bc = bce_logits(rc2.x, pos0 ? 1.f : 0.f);
                r_conf += pos0 ? bc : (ign0 ? bc : 0.f);
            }
            if (nCell == 2) {
                const float bc = bce_logits(rc2.y, pos1 ? 1.f : 0.f);
                r_conf += pos1 ? bc : (ign1 ? bc : 0.f);
            }
        }
    } else {
        // ---- positive path: warp-per-positive, lane-per-channel ----
        const int pcount = min(g_pcount, PMAX);
        const int gw = (b - nMain) * 8 + warp;
        for (int p = gw; p < pcount; p += PBLK * 8) {
            const unsigned pk = g_plist[p];
            const int lev = (int)(pk >> 17);
            const int n   = (int)((pk >> 13) & 15u);
            const int key = (int)(pk & 0x1FFFu);
            int H; const float* feat; const float* label;
            if (lev == 0)      { H = 52; feat = f0; label = lab0; }
            else if (lev == 1) { H = 26; feat = f1; label = lab1; }
            else               { H = 13; feat = f2; label = lab2; }
            const int W = H, HW = H * W;
            const int a  = key / HW;
            const int hw = key - a * HW;

            const float* fb = feat + ((size_t)(n * 255 + a * 85)) * HW + hw;
            const float* Lb = label + ((size_t)(n * HW + hw) * 3 + a) * 85;

            float fv = 0.f, lv = 0.f;
            if (lane < 4) {
                fv = fb[(size_t)lane * HW];
                lv = __ldg(Lb + lane);
            }
            const float rx = __shfl_sync(0xffffffffu, fv, 0);
            const float ry = __shfl_sync(0xffffffffu, fv, 1);
            const float rw = __shfl_sync(0xffffffffu, fv, 2);
            const float rh = __shfl_sync(0xffffffffu, fv, 3);
            const float lx = __shfl_sync(0xffffffffu, lv, 0);
            const float ly = __shfl_sync(0xffffffffu, lv, 1);
            const float lw = __shfl_sync(0xffffffffu, lv, 2);
            const float lh = __shfl_sync(0xffffffffu, lv, 3);

            float ps = 0.f;
            #pragma unroll
            for (int c0 = 0; c0 < NCLS; c0 += 32) {
                const int c = c0 + lane;
                if (c < NCLS) {
                    const float rp = fb[(size_t)(5 + c) * HW];
                    const float lp = __ldg(Lb + 5 + c);
                    ps += bce_logits(rp, lp);
                }
            }
            r_prob += ps;

            if (lane == 0) {
                const float gx = (float)(hw % W);
                const float gy = (float)(hw / W);
                const float stride = c_stride[lev];
                const float aw = c_anchor[lev][a][0];
                const float ah = c_anchor[lev][a][1];
                const float scale = 2.f - lw * lh * (1.f / (416.f * 416.f));
                const float inv_s = __fdividef(1.f, stride);
                const float ox = lx * inv_s - gx;
                const float oy = ly * inv_s - gy;
                const float xy = bce_logits(rx, ox) + bce_logits(ry, oy);
                const float wx = __logf(__fdividef(lw, aw) + 1e-7f);
                const float wy = __logf(__fdividef(lh, ah) + 1e-7f);
                const float dwx = rw - wx, dwy = rh - wy;
                r_reg += scale * (xy + 0.5f * (dwx * dwx + dwy * dwy));
            }
        }
    }

    // ---- block reduction + last-block finalize ----
    #pragma unroll
    for (int o = 16; o; o >>= 1) {
        r_reg  += __shfl_xor_sync(0xffffffffu, r_reg,  o);
        r_conf += __shfl_xor_sync(0xffffffffu, r_conf, o);
        r_prob += __shfl_xor_sync(0xffffffffu, r_prob, o);
    }
    __shared__ float s_r[8], s_c[8], s_p[8];
    if (lane == 0) { s_r[warp] = r_reg; s_c[warp] = r_conf; s_p[warp] = r_prob; }
    __syncthreads();

    if (threadIdx.x == 0) {
        float R = 0.f, C = 0.f, P = 0.f;
        #pragma unroll
        for (int w = 0; w < 8; w++) { R += s_r[w]; C += s_c[w]; P += s_p[w]; }
        atomicAdd(&g_acc[0], (double)R);
        atomicAdd(&g_acc[1], (double)C);
        atomicAdd(&g_acc[2], (double)P);

        __threadfence();
        const unsigned t = atomicAdd(&g_done, 1u);
        if (t == (unsigned)gridDim.x - 1u) {
            const double v0 = atomicAdd(&g_acc[0], 0.0);
            const double v1 = atomicAdd(&g_acc[1], 0.0);
            const double v2 = atomicAdd(&g_acc[2], 0.0);
            const double invN = 1.0 / (double)N;
            out[0] = (float)(v0 * invN);
            out[1] = (float)(v1 * invN);
            out[2] = (float)(v2 * invN);
            g_acc[0] = 0.0; g_acc[1] = 0.0; g_acc[2] = 0.0;
            #pragma unroll
            for (int l = 0; l < NLEV; l++)
                #pragma unroll
                for (int m = 0; m < NBMAX; m++) g_count[l][m] = 0;
            g_pcount = 0;
            g_done = 0u;
            __threadfence();
        }
    }
}

extern "C" void kernel_launch(void* const* d_in, const int* in_sizes, int n_in,
                              void* d_out, int out_size) {
    const float* f0 = (const float*)d_in[0];
    const float* f1 = (const float*)d_in[1];
    const float* f2 = (const float*)d_in[2];
    const float* l0 = (const float*)d_in[3];
    const float* l1 = (const float*)d_in[4];
    const float* l2 = (const float*)d_in[5];

    int N = in_sizes[0] / (255 * 52 * 52);
    if (N > NBMAX) N = NBMAX;

    const int total = N * CPI_ALL;
    const int gblocks = (total + 1023) / 1024;   // 4 cells per thread
    k_gather<<<gblocks, 256>>>(l0, l1, l2, N, total);
    k_loss<<<N * LBPI + PBLK, 256>>>(f0, f1, f2, l0, l1, l2, N, (float*)d_out);
}

// round 10
// speedup vs baseline: 1.8045x; 1.1805x over previous
#include <cuda_runtime.h>
#include <math.h>

#define NLEV 3
#define NBMAX 16
#define MAXB 64
#define NCLS 80
#define PMAX 1024
// main loss blocks per image: lev0 pairs 4056 -> 16, lev1 pairs 1014 -> 4, lev2 scalar 507 -> 2
#define VB0 16
#define VB1 4
#define SB2 2
#define LBPI (VB0 + VB1 + SB2)   // 22 -> N=16 => 352 main blocks
#define PBLK 18                  // positive-path blocks (144 warps)

__constant__ float c_stride[NLEV] = {8.f, 16.f, 32.f};
__constant__ float c_anchor[NLEV][3][2] = {
    {{12.f, 16.f}, {19.f, 36.f}, {40.f, 28.f}},
    {{36.f, 75.f}, {76.f, 55.f}, {72.f, 146.f}},
    {{142.f, 110.f}, {192.f, 243.f}, {459.f, 401.f}}
};

// Persistent scratch; statically zero-initialized; finalize resets all.
__device__ float4   g_boxes[NLEV][NBMAX][MAXB];   // corners x1,y1,x2,y2
__device__ float    g_area [NLEV][NBMAX][MAXB];   // ta/3
__device__ int      g_key  [NLEV][NBMAX][MAXB];   // cell key = a*HW + hw
__device__ int      g_count[NLEV][NBMAX];
__device__ unsigned g_grp  [NLEV][NBMAX];         // group barrier counters
__device__ unsigned g_plist[PMAX];                // packed (lev<<17 | n<<13 | key)
__device__ int      g_pcount;
__device__ unsigned g_gdone;                      // main blocks done gathering
__device__ double   g_acc[3];
__device__ unsigned g_done;

__device__ __forceinline__ float bce_logits(float x, float t) {
    return fmaxf(x, 0.f) - x * t + __logf(1.f + __expf(-fabsf(x)));
}

__global__ void __launch_bounds__(256, 4)
k_yolo(const float* __restrict__ f0, const float* __restrict__ f1,
       const float* __restrict__ f2,
       const float* __restrict__ lab0, const float* __restrict__ lab1,
       const float* __restrict__ lab2,
       int N, float* __restrict__ out) {
    const int b = blockIdx.x;
    const int nMain = N * LBPI;
    const int warp = threadIdx.x >> 5, lane = threadIdx.x & 31;

    float r_reg = 0.f, r_conf = 0.f, r_prob = 0.f;

    if (b < nMain) {
        // ================= main block =================
        const int n = b / LBPI;
        const int r = b - n * LBPI;
        int lev, chunk, H, gs;
        const float* feat; const float* label;
        bool vec;
        if (r < VB0)            { lev = 0; chunk = r;             H = 52; feat = f0; label = lab0; gs = VB0; vec = true; }
        else if (r < VB0 + VB1) { lev = 1; chunk = r - VB0;       H = 26; feat = f1; label = lab1; gs = VB1; vec = true; }
        else                    { lev = 2; chunk = r - VB0 - VB1; H = 13; feat = f2; label = lab2; gs = SB2; vec = false; }
        const int W = H, HW = H * W;
        const int C3 = 3 * HW;

        // ---- issue feature loads (loss path) ----
        int idx0 = 0, a = 0, hw0 = 0;
        float2 rx2 = {0.f,0.f}, ry2 = {0.f,0.f}, rw2 = {0.f,0.f},
               rh2 = {0.f,0.f}, rc2 = {0.f,0.f};
        bool act;
        if (vec) {
            const int pair = chunk * 256 + threadIdx.x;
            act = pair < (C3 >> 1);
            if (act) {
                idx0 = pair * 2;
                a = idx0 / HW; hw0 = idx0 - a * HW;
                const float* fb = feat + ((size_t)(n * 255 + a * 85)) * HW + hw0;
                rx2 = *reinterpret_cast<const float2*>(fb);
                ry2 = *reinterpret_cast<const float2*>(fb + (size_t)HW);
                rw2 = *reinterpret_cast<const float2*>(fb + (size_t)2 * HW);
                rh2 = *reinterpret_cast<const float2*>(fb + (size_t)3 * HW);
                rc2 = *reinterpret_cast<const float2*>(fb + (size_t)4 * HW);
            }
        } else {
            const int idx = chunk * 256 + threadIdx.x;
            act = idx < C3;
            if (act) {
                idx0 = idx;
                a = idx / HW; hw0 = idx - a * HW;
                const float* fb = feat + ((size_t)(n * 255 + a * 85)) * HW + hw0;
                rx2.x = fb[0];
                ry2.x = fb[(size_t)HW];
                rw2.x = fb[(size_t)2 * HW];
                rh2.x = fb[(size_t)3 * HW];
                rc2.x = fb[(size_t)4 * HW];
            }
        }

        // ---- gather my group's conf cells (same instruction window) ----
        {
            const int K = (lev == 2) ? 1 : 2;
            const int base = chunk * 256 + threadIdx.x;
            const int stride_c = gs * 256;
            int   cc[2];
            float cf[2];
            #pragma unroll
            for (int k = 0; k < 2; k++) {
                const int c = base + k * stride_c;
                cc[k] = c;
                const bool v = (k < K) && (c < C3);
                // clamp address for inactive lanes; value unused
                const size_t j = (size_t)(n * C3 + (v ? c : 0));
                cf[k] = v ? __ldg(label + j * 85 + 4) : 0.f;
            }
            #pragma unroll
            for (int k = 0; k < 2; k++) {
                if (cf[k] > 0.f) {                       // rare (~0.08%)
                    const int c  = cc[k];
                    const int hw = c / 3;
                    const int aa = c - hw * 3;
                    const int key = aa * HW + hw;
                    const float* p = label + (size_t)(n * C3 + c) * 85;
                    const float x = __ldg(p + 0), y = __ldg(p + 1);
                    const float w = __ldg(p + 2), h = __ldg(p + 3);
                    const int slot = atomicAdd(&g_count[lev][n], 1);
                    if (slot < MAXB) {
                        g_boxes[lev][n][slot] = make_float4(x - 0.5f * w, y - 0.5f * h,
                                                            x + 0.5f * w, y + 0.5f * h);
                        g_area[lev][n][slot] = w * h * (1.f / 3.f);
                        g_key [lev][n][slot] = key;
                    }
                    const int ps = atomicAdd(&g_pcount, 1);
                    if (ps < PMAX)
                        g_plist[ps] = ((unsigned)lev << 17) | ((unsigned)n << 13) | (unsigned)key;
                }
            }
        }

        // ---- group barrier (16/4/2 blocks) + global gather-done signal ----
        __threadfence();
        __syncthreads();
        if (threadIdx.x == 0) {
            atomicAdd(&g_gdone, 1u);
            atomicAdd(&g_grp[lev][n], 1u);
            volatile unsigned* p = &g_grp[lev][n];
            while (*p < (unsigned)gs) { __nanosleep(32); }
            __threadfence();
        }
        __syncthreads();

        // ---- stage boxes ----
        __shared__ float4 s_box[MAXB];
        __shared__ float  s_ta3[MAXB];
        __shared__ int    s_key[MAXB];
        const int cnt = min(g_count[lev][n], MAXB);
        if (threadIdx.x < cnt) {
            s_box[threadIdx.x] = g_boxes[lev][n][threadIdx.x];
            s_ta3[threadIdx.x] = g_area[lev][n][threadIdx.x];
            s_key[threadIdx.x] = g_key[lev][n][threadIdx.x];
        }
        __syncthreads();

        // ---- conf loss ----
        if (act) {
            const float gy  = (float)(hw0 / W);
            const float gx0 = (float)(hw0 - (hw0 / W) * W);
            const float stride = c_stride[lev];
            const float aw = c_anchor[lev][a][0];
            const float ah = c_anchor[lev][a][1];

            bool pos0 = false, pos1 = false, ign0 = true, ign1 = true;
            const int nCell = vec ? 2 : 1;
            if (cnt > 0) {
                const float ex0 = __expf(-rx2.x), ey0 = __expf(-ry2.x);
                const float d0  = __fdividef(1.f, (1.f + ex0) * (1.f + ey0));
                const float px0 = ((1.f + ey0) * d0 + gx0) * stride;
                const float py0 = ((1.f + ex0) * d0 + gy)  * stride;
                const float pw0 = __expf(rw2.x) * aw, ph0 = __expf(rh2.x) * ah;
                const float ax1 = px0 - 0.5f * pw0, ay1 = py0 - 0.5f * ph0;
                const float ax2 = px0 + 0.5f * pw0, ay2 = py0 + 0.5f * ph0;
                const float pa3a = pw0 * ph0 * (1.f / 3.f);
                float bx1 = 0.f, by1 = 0.f, bx2 = 0.f, by2 = 0.f, pa3b = 0.f;
                if (nCell == 2) {
                    const float ex1 = __expf(-rx2.y), ey1 = __expf(-ry2.y);
                    const float d1  = __fdividef(1.f, (1.f + ex1) * (1.f + ey1));
                    const float px1c = ((1.f + ey1) * d1 + gx0 + 1.f) * stride;
                    const float py1c = ((1.f + ex1) * d1 + gy) * stride;
                    const float pw1 = __expf(rw2.y) * aw, ph1 = __expf(rh2.y) * ah;
                    bx1 = px1c - 0.5f * pw1; by1 = py1c - 0.5f * ph1;
                    bx2 = px1c + 0.5f * pw1; by2 = py1c + 0.5f * ph1;
                    pa3b = pw1 * ph1 * (1.f / 3.f);
                }
                // iou >= 0.5  <=>  inter >= pa/3 + ta/3   (pa,ta > 0)
                #pragma unroll 2
                for (int k = 0; k < cnt; k++) {
                    const float4 t = s_box[k];
                    const float ta3 = s_ta3[k];
                    const int   key = s_key[k];
                    {
                        const float iw = fmaxf(fminf(ax2, t.z) - fmaxf(ax1, t.x), 0.f);
                        const float ih = fmaxf(fminf(ay2, t.w) - fmaxf(ay1, t.y), 0.f);
                        if (iw * ih >= pa3a + ta3) ign0 = false;
                        if (key == idx0) pos0 = true;
                    }
                    if (nCell == 2) {
                        const float iw = fmaxf(fminf(bx2, t.z) - fmaxf(bx1, t.x), 0.f);
                        const float ih = fmaxf(fminf(by2, t.w) - fmaxf(by1, t.y), 0.f);
                        if (iw * ih >= pa3b + ta3) ign1 = false;
                        if (key == idx0 + 1) pos1 = true;
                    }
                }
            }
            {
                const float bc = bce_logits(rc2.x, pos0 ? 1.f : 0.f);
                r_conf += pos0 ? bc : (ign0 ? bc : 0.f);
            }
            if (nCell == 2) {
                const float bc = bce_logits(rc2.y, pos1 ? 1.f : 0.f);
                r_conf += pos1 ? bc : (ign1 ? bc : 0.f);
            }
        }
    } else {
        // ================= positive path =================
        if (threadIdx.x == 0) {
            volatile unsigned* p = &g_gdone;
            while (*p < (unsigned)nMain) { __nanosleep(64); }
            __threadfence();
        }
        __syncthreads();

        const int pcount = min(g_pcount, PMAX);
        const int gw = (b - nMain) * 8 + warp;
        for (int p = gw; p < pcount; p += PBLK * 8) {
            const unsigned pk = g_plist[p];
            const int lev = (int)(pk >> 17);
            const int n   = (int)((pk >> 13) & 15u);
            const int key = (int)(pk & 0x1FFFu);
            int H; const float* feat; const float* label;
            if (lev == 0)      { H = 52; feat = f0; label = lab0; }
            else if (lev == 1) { H = 26; feat = f1; label = lab1; }
            else               { H = 13; feat = f2; label = lab2; }
            const int W = H, HW = H * W;
            const int a  = key / HW;
            const int hw = key - a * HW;

            const float* fb = feat + ((size_t)(n * 255 + a * 85)) * HW + hw;
            const float* Lb = label + ((size_t)(n * HW + hw) * 3 + a) * 85;

            float fv = 0.f, lv = 0.f;
            if (lane < 4) {
                fv = fb[(size_t)lane * HW];
                lv = __ldg(Lb + lane);
            }
            const float rx = __shfl_sync(0xffffffffu, fv, 0);
            const float ry = __shfl_sync(0xffffffffu, fv, 1);
            const float rw = __shfl_sync(0xffffffffu, fv, 2);
            const float rh = __shfl_sync(0xffffffffu, fv, 3);
            const float lx = __shfl_sync(0xffffffffu, lv, 0);
            const float ly = __shfl_sync(0xffffffffu, lv, 1);
            const float lw = __shfl_sync(0xffffffffu, lv, 2);
            const float lh = __shfl_sync(0xffffffffu, lv, 3);

            float ps = 0.f;
            #pragma unroll
            for (int c0 = 0; c0 < NCLS; c0 += 32) {
                const int c = c0 + lane;
                if (c < NCLS) {
                    const float rp = fb[(size_t)(5 + c) * HW];
                    const float lp = __ldg(Lb + 5 + c);
                    ps += bce_logits(rp, lp);
                }
            }
            r_prob += ps;

            if (lane == 0) {
                const float gx = (float)(hw % W);
                const float gy = (float)(hw / W);
                const float stride = c_stride[lev];
                const float aw = c_anchor[lev][a][0];
                const float ah = c_anchor[lev][a][1];
                const float scale = 2.f - lw * lh * (1.f / (416.f * 416.f));
                const float inv_s = __fdividef(1.f, stride);
                const float ox = lx * inv_s - gx;
                const float oy = ly * inv_s - gy;
                const float xy = bce_logits(rx, ox) + bce_logits(ry, oy);
                const float wx = __logf(__fdividef(lw, aw) + 1e-7f);
                const float wy = __logf(__fdividef(lh, ah) + 1e-7f);
                const float dwx = rw - wx, dwy = rh - wy;
                r_reg += scale * (xy + 0.5f * (dwx * dwx + dwy * dwy));
            }
        }
    }

    // ---- block reduction + last-block finalize ----
    #pragma unroll
    for (int o = 16; o; o >>= 1) {
        r_reg  += __shfl_xor_sync(0xffffffffu, r_reg,  o);
        r_conf += __shfl_xor_sync(0xffffffffu, r_conf, o);
        r_prob += __shfl_xor_sync(0xffffffffu, r_prob, o);
    }
    __shared__ float s_r[8], s_c[8], s_p[8];
    if (lane == 0) { s_r[warp] = r_reg; s_c[warp] = r_conf; s_p[warp] = r_prob; }
    __syncthreads();

    if (threadIdx.x == 0) {
        float R = 0.f, C = 0.f, P = 0.f;
        #pragma unroll
        for (int w = 0; w < 8; w++) { R += s_r[w]; C += s_c[w]; P += s_p[w]; }
        atomicAdd(&g_acc[0], (double)R);
        atomicAdd(&g_acc[1], (double)C);
        atomicAdd(&g_acc[2], (double)P);

        __threadfence();
        const unsigned t = atomicAdd(&g_done, 1u);
        if (t == (unsigned)gridDim.x - 1u) {
            const double v0 = atomicAdd(&g_acc[0], 0.0);
            const double v1 = atomicAdd(&g_acc[1], 0.0);
            const double v2 = atomicAdd(&g_acc[2], 0.0);
            const double invN = 1.0 / (double)N;
            out[0] = (float)(v0 * invN);
            out[1] = (float)(v1 * invN);
            out[2] = (float)(v2 * invN);
            g_acc[0] = 0.0; g_acc[1] = 0.0; g_acc[2] = 0.0;
            #pragma unroll
            for (int l = 0; l < NLEV; l++)
                #pragma unroll
                for (int m = 0; m < NBMAX; m++) { g_count[l][m] = 0; g_grp[l][m] = 0u; }
            g_pcount = 0;
            g_gdone = 0u;
            g_done = 0u;
            __threadfence();
        }
    }
}

extern "C" void kernel_launch(void* const* d_in, const int* in_sizes, int n_in,
                              void* d_out, int out_size) {
    const float* f0 = (const float*)d_in[0];
    const float* f1 = (const float*)d_in[1];
    const float* f2 = (const float*)d_in[2];
    const float* l0 = (const float*)d_in[3];
    const float* l1 = (const float*)d_in[4];
    const float* l2 = (const float*)d_in[5];

    int N = in_sizes[0] / (255 * 52 * 52);
    if (N > NBMAX) N = NBMAX;

    k_yolo<<<N * LBPI + PBLK, 256>>>(f0, f1, f2, l0, l1, l2, N, (float*)d_out);
}